// round 7
// baseline (speedup 1.0000x reference)
#include <cuda_runtime.h>
#include <math.h>
#include <stdint.h>

#ifndef M_PI
#define M_PI 3.14159265358979323846
#endif

// Problem shape (fixed by setup_inputs)
#define BB 2
#define NV 4
#define HH 256
#define WW 512
#define HWSZ (HH * WW)            // 131072
#define PP (NV * HWSZ)            // 524288 points per batch
#define TOTAL (BB * PP)           // 1048576 points total
#define NCH 24

#define VOXEL_SIZE 0.1f
#define CONF_W 0.7f
#define OPAC_W 0.3f
#define CONF_THRESH 0.1f
#define OPAC_THRESH 0.01f

#define TABLE_BITS 21
#define TABLE_SIZE (1u << TABLE_BITS)
#define TABLE_MASK (TABLE_SIZE - 1u)
#define EMPTY_KEY 0xFFFFFFFFu
#define INV_SLOT 0xFFFFFFFFu

// Scratch (no runtime allocation allowed -> __device__ globals)
__device__ unsigned int       g_keys[TABLE_SIZE];   // 8 MB
__device__ unsigned long long g_max1[TABLE_SIZE];   // 16 MB
__device__ unsigned long long g_max2[TABLE_SIZE];   // 16 MB
__device__ unsigned int       g_slot[TOTAL];        // 4 MB

// Trig LUTs, filled on-device with the SAME sincosf/input expressions the hot
// kernels previously used -> bit-identical means, zero selection-flip risk.
__device__ float g_sinlon[WW];
__device__ float g_coslon[WW];
__device__ float g_slat[HH];
__device__ float g_clat[HH];

// ---------------------------------------------------------------------------

// 4 independent 16-byte stores per thread -> high MLP, few dependent chains.
#define KEYS16  (TABLE_SIZE / 4)                    // uint4 chunks for g_keys
#define MAX16   (TABLE_SIZE / 2)                    // ulonglong2 chunks per max array
#define CLEAR16 (KEYS16 + 2 * MAX16)
#define CLEAR_THREADS ((CLEAR16 + 3) / 4)
__global__ void __launch_bounds__(256) clear_kernel() {
    // Block 0 additionally fills the trig LUTs (runs concurrently with the
    // clearing done by all blocks; both complete before pass1 launches).
    if (blockIdx.x == 0) {
        const float fx = (float)((double)WW / (2.0 * M_PI));
        const float fy = (float)(-(double)HH / M_PI);
        for (int w = threadIdx.x; w < WW; w += blockDim.x) {
            float lon = ((float)w + 0.5f - (float)(WW / 2)) / fx;
            float sl, cl;
            sincosf(lon, &sl, &cl);
            g_sinlon[w] = sl;
            g_coslon[w] = cl;
        }
        for (int h = threadIdx.x; h < HH; h += blockDim.x) {
            float lat = ((float)h + 0.5f - (float)(HH / 2)) / fy;
            float sl, cl;
            sincosf(lat, &sl, &cl);
            g_slat[h] = sl;
            g_clat[h] = cl;
        }
    }
    unsigned t = blockIdx.x * blockDim.x + threadIdx.x;
#pragma unroll
    for (int k = 0; k < 4; k++) {
        unsigned i = t + (unsigned)k * CLEAR_THREADS;
        if (i < KEYS16) {
            reinterpret_cast<uint4*>(g_keys)[i] =
                make_uint4(EMPTY_KEY, EMPTY_KEY, EMPTY_KEY, EMPTY_KEY);
        } else if (i < KEYS16 + MAX16) {
            ulonglong2 z; z.x = 0ull; z.y = 0ull;
            reinterpret_cast<ulonglong2*>(g_max1)[i - KEYS16] = z;
        } else if (i < CLEAR16) {
            ulonglong2 z; z.x = 0ull; z.y = 0ull;
            reinterpret_cast<ulonglong2*>(g_max2)[i - (KEYS16 + MAX16)] = z;
        }
    }
}

// Find (or claim) the table slot for voxel `key`.
__device__ __forceinline__ unsigned probe_slot(unsigned key) {
    unsigned h = (key * 2654435761u) >> (32 - TABLE_BITS);
    for (;;) {
        unsigned cur = g_keys[h];
        if (cur == key) return h;
        if (cur == EMPTY_KEY) {
            unsigned prev = atomicCAS(&g_keys[h], EMPTY_KEY, key);
            if (prev == EMPTY_KEY || prev == key) return h;
        }
        h = (h + 1u) & TABLE_MASK;
    }
}

// Packed (score, index) key — ONE definition so pass1/pass3 agree bit-exactly.
__device__ __forceinline__ unsigned long long pack_key(float c, float o,
                                                       unsigned p) {
    float score = __fmaf_rn(CONF_W, c, __fmul_rn(OPAC_W, o));
    return ((unsigned long long)__float_as_uint(score) << 32)
         | (unsigned long long)(0xFFFFFFFFu - p);
}

// Identical arithmetic to the R6 passing kernel except trig comes from LUTs
// (bit-identical values by construction).
__device__ __forceinline__ void compute_point(
    int g, const float* __restrict__ depth, const float* __restrict__ opac,
    const float* __restrict__ conf, const float* __restrict__ poses,
    bool& valid, unsigned& key, unsigned long long& packed,
    float& mx, float& my, float& mz)
{
    int b  = g / PP;
    int p  = g - b * PP;
    int n  = p / HWSZ;
    int hw = p - n * HWSZ;
    int h  = hw / WW;
    int w  = hw - h * WW;

    float d = depth[g];
    float c = conf[g];
    float o = opac[g];
    valid = (c > CONF_THRESH) && (o > OPAC_THRESH);

    float slat = __ldg(&g_slat[h]);
    float clat = __ldg(&g_clat[h]);
    float slon = __ldg(&g_sinlon[w]);
    float clon = __ldg(&g_coslon[w]);
    float dx = clat * slon;
    float dy = -slat;
    float dz = clat * clon;

    float px = d * dx, py = d * dy, pz = d * dz;

    const float* M = poses + (size_t)(b * NV + n) * 16;
    mx = M[0] * px + M[1] * py + M[2]  * pz + M[3];
    my = M[4] * px + M[5] * py + M[6]  * pz + M[7];
    mz = M[8] * px + M[9] * py + M[10] * pz + M[11];

    int vx = min(max((int)floorf(mx / VOXEL_SIZE) + 512, 0), 1023);
    int vy = min(max((int)floorf(my / VOXEL_SIZE) + 512, 0), 1023);
    int vz = min(max((int)floorf(mz / VOXEL_SIZE) + 512, 0), 1023);
    unsigned vid = ((unsigned)vx << 20) | ((unsigned)vy << 10) | (unsigned)vz;
    key = ((unsigned)b << 30) | vid;

    packed = pack_key(c, o, (unsigned)p);
}

// Streaming top-2: one atomicMax with return + one fire-and-forget RED.MAX.
__global__ void __launch_bounds__(256) pass1_kernel(
    const float* __restrict__ depth, const float* __restrict__ opac,
    const float* __restrict__ conf,  const float* __restrict__ poses)
{
    int g = blockIdx.x * blockDim.x + threadIdx.x;
    if (g >= TOTAL) return;

    bool valid; unsigned key; unsigned long long pk;
    float mx, my, mz;
    compute_point(g, depth, opac, conf, poses, valid, key, pk, mx, my, mz);

    if (!valid) { g_slot[g] = INV_SLOT; return; }

    unsigned slot = probe_slot(key);
    unsigned long long old = atomicMax(&g_max1[slot], pk);
    unsigned long long v = (pk < old) ? pk : old;   // displaced value
    if (v != 0ull)
        atomicMax(&g_max2[slot], v);                // result unused -> RED

    g_slot[g] = slot;
}

__global__ void __launch_bounds__(256) pass3_kernel(
    const float* __restrict__ depth, const float* __restrict__ cov,
    const float* __restrict__ rot,   const float* __restrict__ opac,
    const float* __restrict__ sh,    const float* __restrict__ conf,
    const float* __restrict__ poses, float* __restrict__ out,
    int write_sel, size_t sel_off)
{
    int g = blockIdx.x * blockDim.x + threadIdx.x;
    if (g >= TOTAL) return;

    bool valid; unsigned key; unsigned long long packed;
    float mx, my, mz;
    compute_point(g, depth, opac, conf, poses, valid, key, packed, mx, my, mz);

    float s = 0.0f;
    unsigned slot = g_slot[g];
    if (slot != INV_SLOT) {
        if (packed == g_max1[slot] || packed == g_max2[slot]) s = 1.0f;
    }

    int b  = g / PP;
    int p  = g - b * PP;
    int n  = p / HWSZ;
    int hw = p - n * HWSZ;

    size_t bn     = (size_t)(b * NV + n);
    size_t base_c = (bn * 3)  * HWSZ + hw;
    size_t base_r = (bn * 4)  * HWSZ + hw;
    size_t base_s = (bn * 12) * HWSZ + hw;

    float f[NCH];
    f[0] = mx; f[1] = my; f[2] = mz;
    f[3] = __ldcs(&cov[base_c]);
    f[4] = __ldcs(&cov[base_c + HWSZ]);
    f[5] = __ldcs(&cov[base_c + 2 * (size_t)HWSZ]);
#pragma unroll
    for (int i = 0; i < 4; i++)
        f[6 + i] = __ldcs(&rot[base_r + (size_t)i * HWSZ]);
    f[10] = opac[g];
#pragma unroll
    for (int i = 0; i < 12; i++)
        f[11 + i] = __ldcs(&sh[base_s + (size_t)i * HWSZ]);
    f[23] = conf[g];

#pragma unroll
    for (int i = 0; i < NCH; i++) f[i] *= s;

    float4* dst = reinterpret_cast<float4*>(out + (size_t)g * NCH);
#pragma unroll
    for (int i = 0; i < 6; i++)
        __stcs(dst + i, make_float4(f[4*i], f[4*i+1], f[4*i+2], f[4*i+3]));

    if (write_sel)
        __stcs(out + sel_off + (size_t)g, s);
}

// ---------------------------------------------------------------------------

extern "C" void kernel_launch(void* const* d_in, const int* in_sizes, int n_in,
                              void* d_out, int out_size) {
    const float* depth = (const float*)d_in[0];
    const float* cov   = (const float*)d_in[1];
    const float* rot   = (const float*)d_in[2];
    const float* opac  = (const float*)d_in[3];
    const float* sh    = (const float*)d_in[4];
    const float* conf  = (const float*)d_in[5];
    const float* poses = (const float*)d_in[6];
    float* out = (float*)d_out;

    size_t featN = (size_t)TOTAL * NCH;
    int write_sel = ((size_t)out_size >= featN + (size_t)TOTAL) ? 1 : 0;

    const int T = 256;
    clear_kernel<<<(CLEAR_THREADS + T - 1) / T, T>>>();
    pass1_kernel<<<(TOTAL + T - 1) / T, T>>>(depth, opac, conf, poses);
    pass3_kernel<<<(TOTAL + T - 1) / T, T>>>(depth, cov, rot, opac, sh, conf,
                                             poses, out, write_sel, featN);
}

// round 8
// speedup vs baseline: 1.0052x; 1.0052x over previous
#include <cuda_runtime.h>
#include <math.h>
#include <stdint.h>

#ifndef M_PI
#define M_PI 3.14159265358979323846
#endif

// Problem shape (fixed by setup_inputs)
#define BB 2
#define NV 4
#define HH 256
#define WW 512
#define HWSZ (HH * WW)            // 131072
#define PP (NV * HWSZ)            // 524288 points per batch
#define TOTAL (BB * PP)           // 1048576 points total
#define NCH 24

#define VOXEL_SIZE 0.1f
#define CONF_W 0.7f
#define OPAC_W 0.3f
#define CONF_THRESH 0.1f
#define OPAC_THRESH 0.01f

#define TABLE_BITS 21
#define TABLE_SIZE (1u << TABLE_BITS)
#define TABLE_MASK (TABLE_SIZE - 1u)
#define EMPTY_KEY 0xFFFFFFFFu
#define INV_SLOT 0xFFFFFFFFu

// Scratch (no runtime allocation allowed -> __device__ globals)
__device__ unsigned int  g_keys[TABLE_SIZE];        // 8 MB
__device__ ulonglong2    g_pair[TABLE_SIZE];        // 32 MB: {max1, max2} interleaved
__device__ unsigned int  g_slot[TOTAL];             // 4 MB

// ---------------------------------------------------------------------------

// 4 independent 16-byte stores per thread -> high MLP, few dependent chains.
#define KEYS16  (TABLE_SIZE / 4)                    // uint4 chunks for g_keys
#define PAIR16  (TABLE_SIZE)                        // ulonglong2 chunks for g_pair
#define CLEAR16 (KEYS16 + PAIR16)
#define CLEAR_THREADS ((CLEAR16 + 3) / 4)
__global__ void __launch_bounds__(256) clear_kernel() {
    unsigned t = blockIdx.x * blockDim.x + threadIdx.x;
#pragma unroll
    for (int k = 0; k < 4; k++) {
        unsigned i = t + (unsigned)k * CLEAR_THREADS;
        if (i < KEYS16) {
            reinterpret_cast<uint4*>(g_keys)[i] =
                make_uint4(EMPTY_KEY, EMPTY_KEY, EMPTY_KEY, EMPTY_KEY);
        } else if (i < CLEAR16) {
            ulonglong2 z; z.x = 0ull; z.y = 0ull;
            g_pair[i - KEYS16] = z;
        }
    }
}

// Find (or claim) the table slot for voxel `key`.
__device__ __forceinline__ unsigned probe_slot(unsigned key) {
    unsigned h = (key * 2654435761u) >> (32 - TABLE_BITS);
    for (;;) {
        unsigned cur = g_keys[h];
        if (cur == key) return h;
        if (cur == EMPTY_KEY) {
            unsigned prev = atomicCAS(&g_keys[h], EMPTY_KEY, key);
            if (prev == EMPTY_KEY || prev == key) return h;
        }
        h = (h + 1u) & TABLE_MASK;
    }
}

// Packed (score, index) key — ONE definition so pass1/pass3 agree bit-exactly.
__device__ __forceinline__ unsigned long long pack_key(float c, float o,
                                                       unsigned p) {
    float score = __fmaf_rn(CONF_W, c, __fmul_rn(OPAC_W, o));
    return ((unsigned long long)__float_as_uint(score) << 32)
         | (unsigned long long)(0xFFFFFFFFu - p);
}

// Identical arithmetic to the R6 passing kernel (proven numerics).
__device__ __forceinline__ void compute_point(
    int g, const float* __restrict__ depth, const float* __restrict__ opac,
    const float* __restrict__ conf, const float* __restrict__ poses,
    bool& valid, unsigned& key, unsigned long long& packed,
    float& mx, float& my, float& mz)
{
    int b  = g / PP;
    int p  = g - b * PP;
    int n  = p / HWSZ;
    int hw = p - n * HWSZ;
    int h  = hw / WW;
    int w  = hw - h * WW;

    float d = depth[g];
    float c = conf[g];
    float o = opac[g];
    valid = (c > CONF_THRESH) && (o > OPAC_THRESH);

    const float fx = (float)((double)WW / (2.0 * M_PI));
    const float fy = (float)(-(double)HH / M_PI);
    float lon = ((float)w + 0.5f - (float)(WW / 2)) / fx;
    float lat = ((float)h + 0.5f - (float)(HH / 2)) / fy;
    float slat, clat, slon, clon;
    sincosf(lat, &slat, &clat);
    sincosf(lon, &slon, &clon);
    float dx = clat * slon;
    float dy = -slat;
    float dz = clat * clon;

    float px = d * dx, py = d * dy, pz = d * dz;

    const float* M = poses + (size_t)(b * NV + n) * 16;
    mx = M[0] * px + M[1] * py + M[2]  * pz + M[3];
    my = M[4] * px + M[5] * py + M[6]  * pz + M[7];
    mz = M[8] * px + M[9] * py + M[10] * pz + M[11];

    int vx = min(max((int)floorf(mx / VOXEL_SIZE) + 512, 0), 1023);
    int vy = min(max((int)floorf(my / VOXEL_SIZE) + 512, 0), 1023);
    int vz = min(max((int)floorf(mz / VOXEL_SIZE) + 512, 0), 1023);
    unsigned vid = ((unsigned)vx << 20) | ((unsigned)vy << 10) | (unsigned)vz;
    key = ((unsigned)b << 30) | vid;

    packed = pack_key(c, o, (unsigned)p);
}

// Warp-aggregated streaming top-2: lanes sharing a voxel key (common, since
// adjacent pixels are << VOXEL_SIZE apart) elect a leader that issues ONE
// atomicMax(max1) + ONE RED(max2) for the whole group.
__global__ void __launch_bounds__(256) pass1_kernel(
    const float* __restrict__ depth, const float* __restrict__ opac,
    const float* __restrict__ conf,  const float* __restrict__ poses)
{
    int g = blockIdx.x * blockDim.x + threadIdx.x;   // grid exact: TOTAL/256

    bool valid; unsigned key; unsigned long long pk;
    float mx, my, mz;
    compute_point(g, depth, opac, conf, poses, valid, key, pk, mx, my, mz);

    unsigned ballot = __ballot_sync(0xFFFFFFFFu, valid);
    unsigned slot = INV_SLOT;
    if (valid) {
        unsigned grp = __match_any_sync(ballot, key);

        // Group top-2 (every member computes it; shuffles are ballot-uniform).
        unsigned long long top1 = 0ull, top2 = 0ull;
#pragma unroll
        for (int i = 0; i < 32; i++) {
            unsigned long long v = __shfl_sync(ballot, pk, i);
            if (grp & (1u << i)) {
                if (v > top1) { top2 = top1; top1 = v; }
                else if (v > top2) top2 = v;
            }
        }

        int leader = __ffs(grp) - 1;
        if ((int)(threadIdx.x & 31u) == leader) {
            slot = probe_slot(key);
            unsigned long long* m1 =
                &reinterpret_cast<unsigned long long*>(g_pair)[2 * (size_t)slot];
            unsigned long long old = atomicMax(m1, top1);
            unsigned long long d1 = (top1 < old) ? top1 : old;  // displaced
            unsigned long long m = (d1 > top2) ? d1 : top2;
            if (m != 0ull)
                atomicMax(m1 + 1, m);               // result unused -> RED
        }
        slot = __shfl_sync(ballot, slot, leader);
    }
    g_slot[g] = slot;
}

__global__ void __launch_bounds__(256) pass3_kernel(
    const float* __restrict__ depth, const float* __restrict__ cov,
    const float* __restrict__ rot,   const float* __restrict__ opac,
    const float* __restrict__ sh,    const float* __restrict__ conf,
    const float* __restrict__ poses, float* __restrict__ out,
    int write_sel, size_t sel_off)
{
    int g = blockIdx.x * blockDim.x + threadIdx.x;
    if (g >= TOTAL) return;

    bool valid; unsigned key; unsigned long long packed;
    float mx, my, mz;
    compute_point(g, depth, opac, conf, poses, valid, key, packed, mx, my, mz);

    float s = 0.0f;
    unsigned slot = g_slot[g];
    if (slot != INV_SLOT) {
        ulonglong2 pr = __ldg(&g_pair[slot]);       // one 16B read for both
        if (packed == pr.x || packed == pr.y) s = 1.0f;
    }

    int b  = g / PP;
    int p  = g - b * PP;
    int n  = p / HWSZ;
    int hw = p - n * HWSZ;

    size_t bn     = (size_t)(b * NV + n);
    size_t base_c = (bn * 3)  * HWSZ + hw;
    size_t base_r = (bn * 4)  * HWSZ + hw;
    size_t base_s = (bn * 12) * HWSZ + hw;

    float f[NCH];
    f[0] = mx; f[1] = my; f[2] = mz;
    f[3] = __ldcs(&cov[base_c]);
    f[4] = __ldcs(&cov[base_c + HWSZ]);
    f[5] = __ldcs(&cov[base_c + 2 * (size_t)HWSZ]);
#pragma unroll
    for (int i = 0; i < 4; i++)
        f[6 + i] = __ldcs(&rot[base_r + (size_t)i * HWSZ]);
    f[10] = opac[g];
#pragma unroll
    for (int i = 0; i < 12; i++)
        f[11 + i] = __ldcs(&sh[base_s + (size_t)i * HWSZ]);
    f[23] = conf[g];

#pragma unroll
    for (int i = 0; i < NCH; i++) f[i] *= s;

    float4* dst = reinterpret_cast<float4*>(out + (size_t)g * NCH);
#pragma unroll
    for (int i = 0; i < 6; i++)
        __stcs(dst + i, make_float4(f[4*i], f[4*i+1], f[4*i+2], f[4*i+3]));

    if (write_sel)
        __stcs(out + sel_off + (size_t)g, s);
}

// ---------------------------------------------------------------------------

extern "C" void kernel_launch(void* const* d_in, const int* in_sizes, int n_in,
                              void* d_out, int out_size) {
    const float* depth = (const float*)d_in[0];
    const float* cov   = (const float*)d_in[1];
    const float* rot   = (const float*)d_in[2];
    const float* opac  = (const float*)d_in[3];
    const float* sh    = (const float*)d_in[4];
    const float* conf  = (const float*)d_in[5];
    const float* poses = (const float*)d_in[6];
    float* out = (float*)d_out;

    size_t featN = (size_t)TOTAL * NCH;
    int write_sel = ((size_t)out_size >= featN + (size_t)TOTAL) ? 1 : 0;

    const int T = 256;
    clear_kernel<<<(CLEAR_THREADS + T - 1) / T, T>>>();
    pass1_kernel<<<(TOTAL + T - 1) / T, T>>>(depth, opac, conf, poses);
    pass3_kernel<<<(TOTAL + T - 1) / T, T>>>(depth, cov, rot, opac, sh, conf,
                                             poses, out, write_sel, featN);
}